// round 2
// baseline (speedup 1.0000x reference)
#include <cuda_runtime.h>
#include <math.h>

// Problem constants
#define BB 4
#define NN 4096
#define CC 256
#define HH 8
#define GG 4
#define DD 32
#define NG 1024               // tokens per group
#define SCALE 0.17677669529663687f  // 1/sqrt(32)

// Scratch (device globals; allocation-free)
__device__ float g_Q[BB * GG * HH * NG * DD];  // [b][g][h][i][d]
__device__ float g_K[BB * GG * HH * NG * DD];
__device__ float g_V[BB * GG * HH * NG * DD];
__device__ float g_O[BB * NN * CC];            // o in permuted order [b][j][h*32+d]

// ---------------------------------------------------------------------------
// Kernel 1: QKV = gather(x, idx) @ w_qkv^T, scattered into Q/K/V [b,g,h,i,d]
// grid: (768/64=12 colblocks, 16384/64=256 rowblocks), 256 threads
// ---------------------------------------------------------------------------
__global__ __launch_bounds__(256) void qkv_kernel(
    const float* __restrict__ x, const int* __restrict__ idx,
    const float* __restrict__ w)
{
    const int cBase = blockIdx.x * 64;          // column base in [0,768)
    const int rblk  = blockIdx.y;               // 0..255
    const int b     = rblk >> 6;                // 64 rowblocks per batch
    const int jBase = (rblk & 63) * 64;         // permuted row base within batch

    __shared__ float As[16][64];
    __shared__ float Bs[16][64];
    __shared__ int   sidx[64];

    const int tid = threadIdx.x;
    if (tid < 64) sidx[tid] = idx[jBase + tid];
    __syncthreads();

    const int ty = tid >> 4, tx = tid & 15;
    const int am = tid >> 2,       ak = (tid & 3) * 4;   // A load: row, k-quad
    const int bc = tid & 63,       bk = (tid >> 6) * 4;  // B load: col, k-quad

    const float* xb = x + (size_t)b * NN * CC;
    const float* arow = xb + (size_t)sidx[am] * CC;

    float acc[4][4] = {};

    for (int k0 = 0; k0 < CC; k0 += 16) {
        float4 av = *(const float4*)(arow + k0 + ak);
        float4 bv = *(const float4*)(w + (size_t)(cBase + bc) * CC + k0 + bk);
        __syncthreads();
        As[ak + 0][am] = av.x; As[ak + 1][am] = av.y;
        As[ak + 2][am] = av.z; As[ak + 3][am] = av.w;
        Bs[bk + 0][bc] = bv.x; Bs[bk + 1][bc] = bv.y;
        Bs[bk + 2][bc] = bv.z; Bs[bk + 3][bc] = bv.w;
        __syncthreads();
#pragma unroll
        for (int kk = 0; kk < 16; kk++) {
            float ar[4], br[4];
            *(float4*)ar = *(float4*)&As[kk][ty * 4];
            *(float4*)br = *(float4*)&Bs[kk][tx * 4];
#pragma unroll
            for (int a = 0; a < 4; a++)
#pragma unroll
                for (int c = 0; c < 4; c++) acc[a][c] += ar[a] * br[c];
        }
    }

    // Epilogue: column -> (s, h, dd); scatter into Q/K/V[b][g][h][i][dd]
    const int cg = cBase + tx * 4;
    const int s  = cg >> 8;
    const int h  = (cg >> 5) & 7;
    const int dd = cg & 31;
    float* dst = (s == 0) ? g_Q : ((s == 1) ? g_K : g_V);
#pragma unroll
    for (int a = 0; a < 4; a++) {
        const int j = jBase + ty * 4 + a;
        const int g = j >> 10;
        const int i = j & 1023;
        size_t off = ((((size_t)(b * GG + g) * HH + h) * NG + i) * DD) + dd;
        *(float4*)&dst[off] = make_float4(acc[a][0], acc[a][1], acc[a][2], acc[a][3]);
    }
}

// ---------------------------------------------------------------------------
// Kernel 2: flash attention per (b,g,h). n=1024, d=32.
// grid: (1024/64=16 qblocks, 128 bgh), 256 threads.
// Thread (ty,tx): owns 4 q-rows (ty) x {4 score cols | 2 out d-cols} (tx).
// ---------------------------------------------------------------------------
__global__ __launch_bounds__(256) void attn_kernel()
{
    const int qblk = blockIdx.x;   // 0..15
    const int bgh  = blockIdx.y;   // 0..127
    const float* Qb = g_Q + (size_t)bgh * NG * DD + (size_t)qblk * 64 * DD;
    const float* Kb = g_K + (size_t)bgh * NG * DD;
    const float* Vb = g_V + (size_t)bgh * NG * DD;

    __shared__ float Qs[64][33];
    __shared__ float Ks[64][33];
    __shared__ float Vs[64][34];
    __shared__ float Ps[64][68];

    const int tid = threadIdx.x;
    const int ty = tid >> 4, tx = tid & 15;

#pragma unroll
    for (int i = 0; i < 8; i++) {
        int e = tid + i * 256;           // 0..2047
        Qs[e >> 5][e & 31] = Qb[e];
    }

    float m[4], l[4], acc[4][2];
#pragma unroll
    for (int a = 0; a < 4; a++) {
        m[a] = -1e30f; l[a] = 0.f; acc[a][0] = 0.f; acc[a][1] = 0.f;
    }

    for (int kb = 0; kb < 16; kb++) {
        __syncthreads();  // prior-iter Ps/Ks/Vs consumers done
#pragma unroll
        for (int i = 0; i < 8; i++) {
            int e = tid + i * 256;
            Ks[e >> 5][e & 31] = Kb[kb * 2048 + e];
            Vs[e >> 5][e & 31] = Vb[kb * 2048 + e];
        }
        __syncthreads();

        // S = Q K^T (4x4 per thread)
        float s[4][4] = {};
#pragma unroll
        for (int kk = 0; kk < 32; kk++) {
            float qr[4], kr[4];
#pragma unroll
            for (int a = 0; a < 4; a++) qr[a] = Qs[ty * 4 + a][kk];
#pragma unroll
            for (int c = 0; c < 4; c++) kr[c] = Ks[tx * 4 + c][kk];
#pragma unroll
            for (int a = 0; a < 4; a++)
#pragma unroll
                for (int c = 0; c < 4; c++) s[a][c] += qr[a] * kr[c];
        }

        // Online softmax update per q-row (allreduce over 16-lane tx group)
#pragma unroll
        for (int a = 0; a < 4; a++) {
            float rmax = -1e30f;
#pragma unroll
            for (int c = 0; c < 4; c++) {
                s[a][c] *= SCALE;
                rmax = fmaxf(rmax, s[a][c]);
            }
#pragma unroll
            for (int off = 8; off; off >>= 1)
                rmax = fmaxf(rmax, __shfl_xor_sync(0xffffffffu, rmax, off));
            float mnew  = fmaxf(m[a], rmax);
            float alpha = __expf(m[a] - mnew);
            float lsum  = 0.f;
#pragma unroll
            for (int c = 0; c < 4; c++) {
                float p = __expf(s[a][c] - mnew);
                s[a][c] = p;
                lsum += p;
            }
#pragma unroll
            for (int off = 8; off; off >>= 1)
                lsum += __shfl_xor_sync(0xffffffffu, lsum, off);
            m[a] = mnew;
            l[a] = l[a] * alpha + lsum;
            acc[a][0] *= alpha;
            acc[a][1] *= alpha;
            *(float4*)&Ps[ty * 4 + a][tx * 4] =
                make_float4(s[a][0], s[a][1], s[a][2], s[a][3]);
        }
        __syncthreads();

        // O += P @ V  (4 rows x 2 d-cols per thread)
#pragma unroll
        for (int c4 = 0; c4 < 64; c4 += 4) {
            float4 p4[4];
#pragma unroll
            for (int a = 0; a < 4; a++) p4[a] = *(float4*)&Ps[ty * 4 + a][c4];
#pragma unroll
            for (int cc = 0; cc < 4; cc++) {
                float2 v2 = *(float2*)&Vs[c4 + cc][tx * 2];
                const float* pf;
#pragma unroll
                for (int a = 0; a < 4; a++) {
                    pf = (const float*)&p4[a];
                    acc[a][0] += pf[cc] * v2.x;
                    acc[a][1] += pf[cc] * v2.y;
                }
            }
        }
    }

    // Finalize: o_perm[b, g*1024+i, h*32+dd]
    const int b = bgh >> 5, g = (bgh >> 3) & 3, h = bgh & 7;
#pragma unroll
    for (int a = 0; a < 4; a++) {
        float inv = 1.f / l[a];
        int i = qblk * 64 + ty * 4 + a;
        size_t row = (size_t)b * NN + (size_t)g * NG + i;
        float2 o2 = make_float2(acc[a][0] * inv, acc[a][1] * inv);
        *(float2*)&g_O[row * CC + h * DD + tx * 2] = o2;
    }
}

// ---------------------------------------------------------------------------
// Kernel 3: out[b, idx[j], :] = o_perm[b, j, :] @ w_proj^T + b_proj
// grid: (256/64=4 colblocks, 256 rowblocks), 256 threads
// ---------------------------------------------------------------------------
__global__ __launch_bounds__(256) void proj_kernel(
    const int* __restrict__ idx, const float* __restrict__ w,
    const float* __restrict__ bias, float* __restrict__ out)
{
    const int cBase = blockIdx.x * 64;
    const int rblk  = blockIdx.y;
    const int b     = rblk >> 6;
    const int jBase = (rblk & 63) * 64;

    __shared__ float As[16][64];
    __shared__ float Bs[16][64];
    __shared__ int   sidx[64];

    const int tid = threadIdx.x;
    if (tid < 64) sidx[tid] = idx[jBase + tid];

    const int ty = tid >> 4, tx = tid & 15;
    const int am = tid >> 2,  ak = (tid & 3) * 4;
    const int bc = tid & 63,  bk = (tid >> 6) * 4;

    const float* Ab = g_O + ((size_t)b * NN + jBase) * CC;
    float acc[4][4] = {};

    for (int k0 = 0; k0 < CC; k0 += 16) {
        float4 av = *(const float4*)(Ab + (size_t)am * CC + k0 + ak);
        float4 bv = *(const float4*)(w + (size_t)(cBase + bc) * CC + k0 + bk);
        __syncthreads();
        As[ak + 0][am] = av.x; As[ak + 1][am] = av.y;
        As[ak + 2][am] = av.z; As[ak + 3][am] = av.w;
        Bs[bk + 0][bc] = bv.x; Bs[bk + 1][bc] = bv.y;
        Bs[bk + 2][bc] = bv.z; Bs[bk + 3][bc] = bv.w;
        __syncthreads();
#pragma unroll
        for (int kk = 0; kk < 16; kk++) {
            float ar[4], br[4];
            *(float4*)ar = *(float4*)&As[kk][ty * 4];
            *(float4*)br = *(float4*)&Bs[kk][tx * 4];
#pragma unroll
            for (int a = 0; a < 4; a++)
#pragma unroll
                for (int c = 0; c < 4; c++) acc[a][c] += ar[a] * br[c];
        }
    }

    float4 bv = *(const float4*)&bias[cBase + tx * 4];
#pragma unroll
    for (int a = 0; a < 4; a++) {
        int orow = sidx[ty * 4 + a];   // inverse permutation as scatter
        float4 r = make_float4(acc[a][0] + bv.x, acc[a][1] + bv.y,
                               acc[a][2] + bv.z, acc[a][3] + bv.w);
        *(float4*)&out[((size_t)b * NN + orow) * CC + cBase + tx * 4] = r;
    }
}

// ---------------------------------------------------------------------------
extern "C" void kernel_launch(void* const* d_in, const int* in_sizes, int n_in,
                              void* d_out, int out_size)
{
    (void)in_sizes; (void)n_in; (void)out_size;
    const float* x      = (const float*)d_in[0];
    const int*   idx    = (const int*)d_in[1];
    const float* w_qkv  = (const float*)d_in[2];
    const float* w_proj = (const float*)d_in[3];
    const float* b_proj = (const float*)d_in[4];
    float* out = (float*)d_out;

    qkv_kernel<<<dim3(12, 256), 256>>>(x, idx, w_qkv);
    attn_kernel<<<dim3(16, 128), 256>>>();
    proj_kernel<<<dim3(4, 256), 256>>>(idx, w_proj, b_proj, out);
}

// round 3
// speedup vs baseline: 1.6148x; 1.6148x over previous
#include <cuda_runtime.h>
#include <math.h>
#include <stdint.h>

// Problem constants
#define BB 4
#define NN 4096
#define CC 256
#define HH 8
#define GG 4
#define DD 32
#define NG 1024
#define SCALE 0.17677669529663687f  // 1/sqrt(32)

// Scratch (device globals; allocation-free)
__device__ float g_Q[BB * GG * HH * NG * DD];  // [b][g][h][i][d]
__device__ float g_K[BB * GG * HH * NG * DD];
__device__ float g_V[BB * GG * HH * NG * DD];
__device__ float g_O[BB * NN * CC];            // attention out, permuted order

// ---------------------------------------------------------------------------
// mma.sync m16n8k8 tf32 helpers
// ---------------------------------------------------------------------------
__device__ __forceinline__ void mma8(float c[4], const uint32_t a[4],
                                     uint32_t b0, uint32_t b1) {
    asm volatile(
        "mma.sync.aligned.m16n8k8.row.col.f32.tf32.tf32.f32 "
        "{%0,%1,%2,%3}, {%4,%5,%6,%7}, {%8,%9}, {%0,%1,%2,%3};"
        : "+f"(c[0]), "+f"(c[1]), "+f"(c[2]), "+f"(c[3])
        : "r"(a[0]), "r"(a[1]), "r"(a[2]), "r"(a[3]), "r"(b0), "r"(b1));
}
__device__ __forceinline__ uint32_t to_tf32(float x) {
    uint32_t h; asm("cvt.rna.tf32.f32 %0, %1;" : "=r"(h) : "f"(x)); return h;
}
__device__ __forceinline__ void split_tf32(float x, uint32_t& hi, uint32_t& lo) {
    asm("cvt.rna.tf32.f32 %0, %1;" : "=r"(hi) : "f"(x));
    float r = x - __uint_as_float(hi);
    asm("cvt.rna.tf32.f32 %0, %1;" : "=r"(lo) : "f"(r));
}

// ---------------------------------------------------------------------------
// Kernel 1: QKV = gather(x, idx) @ w_qkv^T  (plain tf32 mma)
// block tile 128x64, 8 warps (4m x 2n), warp tile 32x32. grid (12, 128)
// ---------------------------------------------------------------------------
__global__ __launch_bounds__(256) void qkv_kernel(
    const float* __restrict__ x, const int* __restrict__ idx,
    const float* __restrict__ w)
{
    const int cBase = blockIdx.x * 64;
    const int rblk  = blockIdx.y;
    const int b     = rblk >> 5;
    const int jBase = (rblk & 31) * 128;

    __shared__ float As[128][20];
    __shared__ float Bs[64][20];
    __shared__ int   sidx[128];

    const int tid = threadIdx.x;
    const int warp = tid >> 5, lane = tid & 31;
    const int g = lane >> 2, t = lane & 3;
    const int wm = warp >> 1, wn = warp & 1;

    if (tid < 128) sidx[tid] = idx[jBase + tid];
    __syncthreads();

    const float* arow = x + ((size_t)b * NN + sidx[tid >> 1]) * CC + (tid & 1) * 8;
    const float* brow = w + (size_t)(cBase + (tid & 63)) * CC + (tid >> 6) * 4;
    const int ars = tid >> 1, akq = (tid & 1) * 8;
    const int brs = tid & 63, bkq = (tid >> 6) * 4;

    float acc[2][4][4] = {};

    for (int k0 = 0; k0 < CC; k0 += 16) {
        float4 a0 = *(const float4*)(arow + k0);
        float4 a1 = *(const float4*)(arow + k0 + 4);
        float4 bv = *(const float4*)(brow + k0);
        __syncthreads();
        *(float4*)&As[ars][akq]     = a0;
        *(float4*)&As[ars][akq + 4] = a1;
        *(float4*)&Bs[brs][bkq]     = bv;
        __syncthreads();
#pragma unroll
        for (int ks = 0; ks < 2; ks++) {
            uint32_t af[2][4];
#pragma unroll
            for (int mt = 0; mt < 2; mt++) {
                int rb = wm * 32 + mt * 16;
                af[mt][0] = to_tf32(As[rb + g][ks * 8 + t]);
                af[mt][1] = to_tf32(As[rb + g + 8][ks * 8 + t]);
                af[mt][2] = to_tf32(As[rb + g][ks * 8 + t + 4]);
                af[mt][3] = to_tf32(As[rb + g + 8][ks * 8 + t + 4]);
            }
#pragma unroll
            for (int nt = 0; nt < 4; nt++) {
                uint32_t b0 = to_tf32(Bs[wn * 32 + nt * 8 + g][ks * 8 + t]);
                uint32_t b1 = to_tf32(Bs[wn * 32 + nt * 8 + g][ks * 8 + t + 4]);
                mma8(acc[0][nt], af[0], b0, b1);
                mma8(acc[1][nt], af[1], b0, b1);
            }
        }
    }

    // Epilogue: scatter into Q/K/V[b][g][h][i][dd]
    const int cwb = cBase + wn * 32;          // multiple of 32
    const int s = cwb >> 8, h = (cwb >> 5) & 7;
    float* dst = (s == 0) ? g_Q : ((s == 1) ? g_K : g_V);
#pragma unroll
    for (int mt = 0; mt < 2; mt++) {
#pragma unroll
        for (int r = 0; r < 2; r++) {
            int j = jBase + wm * 32 + mt * 16 + g + r * 8;
            int gg = j >> 10, i = j & 1023;
            size_t off = (((size_t)(b * GG + gg) * HH + h) * NG + i) * DD;
#pragma unroll
            for (int nt = 0; nt < 4; nt++) {
                *(float2*)&dst[off + nt * 8 + 2 * t] =
                    make_float2(acc[mt][nt][r * 2], acc[mt][nt][r * 2 + 1]);
            }
        }
    }
}

// ---------------------------------------------------------------------------
// Kernel 2: flash attention per (bgh, 64-row q-block). 4 warps, each 16 q rows.
// S and PV via 3xTF32 mma (fp32-class accuracy). grid (16, 128), 128 threads.
// ---------------------------------------------------------------------------
#define PADK 36
#define PADP 68

__global__ __launch_bounds__(128) void attn_kernel()
{
    const int qblk = blockIdx.x;
    const int bgh  = blockIdx.y;
    const float* Qb = g_Q + (size_t)bgh * NG * DD + (size_t)qblk * 64 * DD;
    const float* Kb = g_K + (size_t)bgh * NG * DD;
    const float* Vb = g_V + (size_t)bgh * NG * DD;

    __shared__ float Ks[64][PADK];
    __shared__ float Vs[64][PADK];
    __shared__ float Ps[64][PADP];

    const int tid = threadIdx.x;
    const int warp = tid >> 5, lane = tid & 31;
    const int g = lane >> 2, t = lane & 3;
    const int rbase = warp * 16;

    // Q fragments (pre-scaled, hi/lo split), resident in registers
    uint32_t qhi[4][4], qlo[4][4];
    {
        const float* Qw = Qb + rbase * DD;
#pragma unroll
        for (int ks = 0; ks < 4; ks++) {
            split_tf32(Qw[g * 32 + ks * 8 + t] * SCALE,          qhi[ks][0], qlo[ks][0]);
            split_tf32(Qw[(g + 8) * 32 + ks * 8 + t] * SCALE,    qhi[ks][1], qlo[ks][1]);
            split_tf32(Qw[g * 32 + ks * 8 + t + 4] * SCALE,      qhi[ks][2], qlo[ks][2]);
            split_tf32(Qw[(g + 8) * 32 + ks * 8 + t + 4] * SCALE, qhi[ks][3], qlo[ks][3]);
        }
    }

    float m0 = -1e30f, m1 = -1e30f, l0 = 0.f, l1 = 0.f;
    float oc[4][4] = {};

    for (int kb = 0; kb < 16; kb++) {
        __syncthreads();
#pragma unroll
        for (int i = 0; i < 4; i++) {
            int e4 = tid + i * 128;         // float4 slot 0..511
            int row = e4 >> 3;
            int col = (e4 & 7) * 4;
            *(float4*)&Ks[row][col] = *(const float4*)(Kb + kb * 2048 + e4 * 4);
            *(float4*)&Vs[row][col] = *(const float4*)(Vb + kb * 2048 + e4 * 4);
        }
        __syncthreads();

        // S = Q K^T (3xTF32)
        float sc[8][4];
#pragma unroll
        for (int nt = 0; nt < 8; nt++) {
            sc[nt][0] = sc[nt][1] = sc[nt][2] = sc[nt][3] = 0.f;
#pragma unroll
            for (int ks = 0; ks < 4; ks++) {
                uint32_t bh0, bl0, bh1, bl1;
                split_tf32(Ks[nt * 8 + g][ks * 8 + t],     bh0, bl0);
                split_tf32(Ks[nt * 8 + g][ks * 8 + t + 4], bh1, bl1);
                mma8(sc[nt], qhi[ks], bh0, bh1);
                mma8(sc[nt], qhi[ks], bl0, bl1);
                mma8(sc[nt], qlo[ks], bh0, bh1);
            }
        }

        // Online softmax (rows g and g+8; 4-thread group spans the 64 cols)
        float rmax0 = -1e30f, rmax1 = -1e30f;
#pragma unroll
        for (int nt = 0; nt < 8; nt++) {
            rmax0 = fmaxf(rmax0, fmaxf(sc[nt][0], sc[nt][1]));
            rmax1 = fmaxf(rmax1, fmaxf(sc[nt][2], sc[nt][3]));
        }
        rmax0 = fmaxf(rmax0, __shfl_xor_sync(0xffffffffu, rmax0, 1));
        rmax0 = fmaxf(rmax0, __shfl_xor_sync(0xffffffffu, rmax0, 2));
        rmax1 = fmaxf(rmax1, __shfl_xor_sync(0xffffffffu, rmax1, 1));
        rmax1 = fmaxf(rmax1, __shfl_xor_sync(0xffffffffu, rmax1, 2));
        float mn0 = fmaxf(m0, rmax0), mn1 = fmaxf(m1, rmax1);
        float al0 = __expf(m0 - mn0), al1 = __expf(m1 - mn1);
        float s0 = 0.f, s1 = 0.f;
#pragma unroll
        for (int nt = 0; nt < 8; nt++) {
            sc[nt][0] = __expf(sc[nt][0] - mn0); s0 += sc[nt][0];
            sc[nt][1] = __expf(sc[nt][1] - mn0); s0 += sc[nt][1];
            sc[nt][2] = __expf(sc[nt][2] - mn1); s1 += sc[nt][2];
            sc[nt][3] = __expf(sc[nt][3] - mn1); s1 += sc[nt][3];
        }
        s0 += __shfl_xor_sync(0xffffffffu, s0, 1);
        s0 += __shfl_xor_sync(0xffffffffu, s0, 2);
        s1 += __shfl_xor_sync(0xffffffffu, s1, 1);
        s1 += __shfl_xor_sync(0xffffffffu, s1, 2);
        m0 = mn0; m1 = mn1;
        l0 = l0 * al0 + s0;
        l1 = l1 * al1 + s1;
#pragma unroll
        for (int nt = 0; nt < 4; nt++) {
            oc[nt][0] *= al0; oc[nt][1] *= al0;
            oc[nt][2] *= al1; oc[nt][3] *= al1;
        }

        // P -> smem (warp-private rows), then PV (3xTF32)
#pragma unroll
        for (int nt = 0; nt < 8; nt++) {
            *(float2*)&Ps[rbase + g][nt * 8 + 2 * t]     = make_float2(sc[nt][0], sc[nt][1]);
            *(float2*)&Ps[rbase + g + 8][nt * 8 + 2 * t] = make_float2(sc[nt][2], sc[nt][3]);
        }
        __syncwarp();

#pragma unroll
        for (int ks = 0; ks < 8; ks++) {
            uint32_t ah[4], al[4];
            split_tf32(Ps[rbase + g][ks * 8 + t],         ah[0], al[0]);
            split_tf32(Ps[rbase + g + 8][ks * 8 + t],     ah[1], al[1]);
            split_tf32(Ps[rbase + g][ks * 8 + t + 4],     ah[2], al[2]);
            split_tf32(Ps[rbase + g + 8][ks * 8 + t + 4], ah[3], al[3]);
#pragma unroll
            for (int nt = 0; nt < 4; nt++) {
                uint32_t bh0, bl0, bh1, bl1;
                split_tf32(Vs[ks * 8 + t][nt * 8 + g],     bh0, bl0);
                split_tf32(Vs[ks * 8 + t + 4][nt * 8 + g], bh1, bl1);
                mma8(oc[nt], ah, bh0, bh1);
                mma8(oc[nt], ah, bl0, bl1);
                mma8(oc[nt], al, bh0, bh1);
            }
        }
    }

    // Finalize
    const int b = bgh >> 5, gg = (bgh >> 3) & 3, h = bgh & 7;
    float inv0 = 1.f / l0, inv1 = 1.f / l1;
    int i0 = qblk * 64 + rbase + g;
    size_t row0 = ((size_t)b * NN + (size_t)gg * NG + i0) * CC + h * DD;
    size_t row1 = row0 + (size_t)8 * CC;
#pragma unroll
    for (int nt = 0; nt < 4; nt++) {
        *(float2*)&g_O[row0 + nt * 8 + 2 * t] =
            make_float2(oc[nt][0] * inv0, oc[nt][1] * inv0);
        *(float2*)&g_O[row1 + nt * 8 + 2 * t] =
            make_float2(oc[nt][2] * inv1, oc[nt][3] * inv1);
    }
}

// ---------------------------------------------------------------------------
// Kernel 3: out[b, idx[j], :] = o_perm[b, j, :] @ w_proj^T + bias
// same tiling as qkv. grid (4, 128)
// ---------------------------------------------------------------------------
__global__ __launch_bounds__(256) void proj_kernel(
    const int* __restrict__ idx, const float* __restrict__ w,
    const float* __restrict__ bias, float* __restrict__ out)
{
    const int cBase = blockIdx.x * 64;
    const int rblk  = blockIdx.y;
    const int b     = rblk >> 5;
    const int jBase = (rblk & 31) * 128;

    __shared__ float As[128][20];
    __shared__ float Bs[64][20];
    __shared__ int   sidx[128];

    const int tid = threadIdx.x;
    const int warp = tid >> 5, lane = tid & 31;
    const int g = lane >> 2, t = lane & 3;
    const int wm = warp >> 1, wn = warp & 1;

    if (tid < 128) sidx[tid] = idx[jBase + tid];

    const float* arow = g_O + ((size_t)b * NN + jBase + (tid >> 1)) * CC + (tid & 1) * 8;
    const float* brow = w + (size_t)(cBase + (tid & 63)) * CC + (tid >> 6) * 4;
    const int ars = tid >> 1, akq = (tid & 1) * 8;
    const int brs = tid & 63, bkq = (tid >> 6) * 4;

    float acc[2][4][4] = {};

    for (int k0 = 0; k0 < CC; k0 += 16) {
        float4 a0 = *(const float4*)(arow + k0);
        float4 a1 = *(const float4*)(arow + k0 + 4);
        float4 bv = *(const float4*)(brow + k0);
        __syncthreads();
        *(float4*)&As[ars][akq]     = a0;
        *(float4*)&As[ars][akq + 4] = a1;
        *(float4*)&Bs[brs][bkq]     = bv;
        __syncthreads();
#pragma unroll
        for (int ks = 0; ks < 2; ks++) {
            uint32_t af[2][4];
#pragma unroll
            for (int mt = 0; mt < 2; mt++) {
                int rb = wm * 32 + mt * 16;
                af[mt][0] = to_tf32(As[rb + g][ks * 8 + t]);
                af[mt][1] = to_tf32(As[rb + g + 8][ks * 8 + t]);
                af[mt][2] = to_tf32(As[rb + g][ks * 8 + t + 4]);
                af[mt][3] = to_tf32(As[rb + g + 8][ks * 8 + t + 4]);
            }
#pragma unroll
            for (int nt = 0; nt < 4; nt++) {
                uint32_t b0 = to_tf32(Bs[wn * 32 + nt * 8 + g][ks * 8 + t]);
                uint32_t b1 = to_tf32(Bs[wn * 32 + nt * 8 + g][ks * 8 + t + 4]);
                mma8(acc[0][nt], af[0], b0, b1);
                mma8(acc[1][nt], af[1], b0, b1);
            }
        }
    }

    // Epilogue: bias + inverse-permutation row scatter
    float2 bb[4];
#pragma unroll
    for (int nt = 0; nt < 4; nt++)
        bb[nt] = *(const float2*)&bias[cBase + wn * 32 + nt * 8 + 2 * t];

#pragma unroll
    for (int mt = 0; mt < 2; mt++) {
#pragma unroll
        for (int r = 0; r < 2; r++) {
            int jl = wm * 32 + mt * 16 + g + r * 8;
            int orow = sidx[jl];
            size_t base = ((size_t)b * NN + orow) * CC + cBase + wn * 32;
#pragma unroll
            for (int nt = 0; nt < 4; nt++) {
                *(float2*)&out[base + nt * 8 + 2 * t] =
                    make_float2(acc[mt][nt][r * 2] + bb[nt].x,
                                acc[mt][nt][r * 2 + 1] + bb[nt].y);
            }
        }
    }
}

// ---------------------------------------------------------------------------
extern "C" void kernel_launch(void* const* d_in, const int* in_sizes, int n_in,
                              void* d_out, int out_size)
{
    (void)in_sizes; (void)n_in; (void)out_size;
    const float* x      = (const float*)d_in[0];
    const int*   idx    = (const int*)d_in[1];
    const float* w_qkv  = (const float*)d_in[2];
    const float* w_proj = (const float*)d_in[3];
    const float* b_proj = (const float*)d_in[4];
    float* out = (float*)d_out;

    qkv_kernel<<<dim3(12, 128), 256>>>(x, idx, w_qkv);
    attn_kernel<<<dim3(16, 128), 128>>>();
    proj_kernel<<<dim3(4, 128), 256>>>(idx, w_proj, b_proj, out);
}

// round 4
// speedup vs baseline: 1.7138x; 1.0613x over previous
#include <cuda_runtime.h>
#include <math.h>
#include <stdint.h>

// Problem constants
#define BB 4
#define NN 4096
#define CC 256
#define HH 8
#define GG 4
#define DD 32
#define NG 1024
#define SCALE 0.17677669529663687f  // 1/sqrt(32)

// Scratch (device globals; allocation-free)
__device__ float g_Q[BB * GG * HH * NG * DD];  // [b][g][h][i][d]
__device__ float g_K[BB * GG * HH * NG * DD];
__device__ float g_V[BB * GG * HH * NG * DD];
__device__ float g_O[BB * NN * CC];            // attention out, permuted order

// ---------------------------------------------------------------------------
// PTX helpers
// ---------------------------------------------------------------------------
__device__ __forceinline__ void mma8(float c[4], const uint32_t a[4],
                                     uint32_t b0, uint32_t b1) {
    asm volatile(
        "mma.sync.aligned.m16n8k8.row.col.f32.tf32.tf32.f32 "
        "{%0,%1,%2,%3}, {%4,%5,%6,%7}, {%8,%9}, {%0,%1,%2,%3};"
        : "+f"(c[0]), "+f"(c[1]), "+f"(c[2]), "+f"(c[3])
        : "r"(a[0]), "r"(a[1]), "r"(a[2]), "r"(a[3]), "r"(b0), "r"(b1));
}
__device__ __forceinline__ uint32_t to_tf32(float x) {
    uint32_t h; asm("cvt.rna.tf32.f32 %0, %1;" : "=r"(h) : "f"(x)); return h;
}
__device__ __forceinline__ void split_tf32(float x, uint32_t& hi, uint32_t& lo) {
    asm("cvt.rna.tf32.f32 %0, %1;" : "=r"(hi) : "f"(x));
    float r = x - __uint_as_float(hi);
    asm("cvt.rna.tf32.f32 %0, %1;" : "=r"(lo) : "f"(r));
}
__device__ __forceinline__ uint32_t sptr(const void* p) {
    return (uint32_t)__cvta_generic_to_shared(p);
}
// ldmatrix x4 on fp32 data: each 8x8 fp32 tile (= 8x16 b16) lands with the
// exact mma fragment distribution (lane -> row lane/4, 32-bit col lane%4).
__device__ __forceinline__ void ldsm4(uint32_t addr, uint32_t& r0, uint32_t& r1,
                                      uint32_t& r2, uint32_t& r3) {
    asm volatile("ldmatrix.sync.aligned.m8n8.x4.shared.b16 {%0,%1,%2,%3}, [%4];"
                 : "=r"(r0), "=r"(r1), "=r"(r2), "=r"(r3) : "r"(addr));
}

// ---------------------------------------------------------------------------
// Kernel 1: QKV = gather(x, idx) @ w_qkv^T  (tf32 mma, ldmatrix fragments)
// block tile 128x64, 8 warps (4m x 2n), warp tile 32x32, k-slab 32. grid(12,128)
// ---------------------------------------------------------------------------
__global__ __launch_bounds__(256) void qkv_kernel(
    const float* __restrict__ x, const int* __restrict__ idx,
    const float* __restrict__ w)
{
    const int cBase = blockIdx.x * 64;
    const int rblk  = blockIdx.y;
    const int b     = rblk >> 5;
    const int jBase = (rblk & 31) * 128;

    __shared__ float As[128][36];
    __shared__ float Bs[64][36];
    __shared__ int   sidx[128];

    const int tid = threadIdx.x;
    const int warp = tid >> 5, lane = tid & 31;
    const int g = lane >> 2, t = lane & 3;
    const int wm = warp >> 1, wn = warp & 1;
    const int mat = lane >> 3, r8 = lane & 7;

    if (tid < 128) sidx[tid] = idx[jBase + tid];
    __syncthreads();

    const float* arow = x + ((size_t)b * NN + sidx[tid >> 1]) * CC + (tid & 1) * 16;
    const float* brow = w + (size_t)(cBase + (tid & 63)) * CC + (tid >> 6) * 8;
    const int ar = tid >> 1, akh = (tid & 1) * 16;
    const int br = tid & 63, bkh = (tid >> 6) * 8;

    float4 pa[4], pb[2];
#pragma unroll
    for (int i = 0; i < 4; i++) pa[i] = *(const float4*)(arow + i * 4);
    pb[0] = *(const float4*)(brow);
    pb[1] = *(const float4*)(brow + 4);

    // ldmatrix lane base addresses
    const uint32_t aAddr = sptr(&As[wm * 32 + (mat & 1) * 8 + r8][(mat >> 1) * 4]);
    const uint32_t bAddr = sptr(&Bs[wn * 32 + (mat >> 1) * 8 + r8][(mat & 1) * 4]);

    float acc[2][4][4] = {};

    for (int s = 0; s < 8; s++) {
        __syncthreads();
        *(float4*)&As[ar][akh]      = pa[0];
        *(float4*)&As[ar][akh + 4]  = pa[1];
        *(float4*)&As[ar][akh + 8]  = pa[2];
        *(float4*)&As[ar][akh + 12] = pa[3];
        *(float4*)&Bs[br][bkh]      = pb[0];
        *(float4*)&Bs[br][bkh + 4]  = pb[1];
        __syncthreads();
        if (s < 7) {
            const float* an = arow + (s + 1) * 32;
#pragma unroll
            for (int i = 0; i < 4; i++) pa[i] = *(const float4*)(an + i * 4);
            pb[0] = *(const float4*)(brow + (s + 1) * 32);
            pb[1] = *(const float4*)(brow + (s + 1) * 32 + 4);
        }
#pragma unroll
        for (int ks = 0; ks < 4; ks++) {
            uint32_t af[2][4];
#pragma unroll
            for (int mt = 0; mt < 2; mt++) {
                ldsm4(aAddr + (uint32_t)(mt * 16 * 36 + ks * 8) * 4,
                      af[mt][0], af[mt][1], af[mt][2], af[mt][3]);
#pragma unroll
                for (int i = 0; i < 4; i++) af[mt][i] = to_tf32(__uint_as_float(af[mt][i]));
            }
#pragma unroll
            for (int np = 0; np < 2; np++) {
                uint32_t bf[4];
                ldsm4(bAddr + (uint32_t)(np * 16 * 36 + ks * 8) * 4,
                      bf[0], bf[1], bf[2], bf[3]);
#pragma unroll
                for (int i = 0; i < 4; i++) bf[i] = to_tf32(__uint_as_float(bf[i]));
                mma8(acc[0][np * 2],     af[0], bf[0], bf[1]);
                mma8(acc[1][np * 2],     af[1], bf[0], bf[1]);
                mma8(acc[0][np * 2 + 1], af[0], bf[2], bf[3]);
                mma8(acc[1][np * 2 + 1], af[1], bf[2], bf[3]);
            }
        }
    }

    // Epilogue: scatter into Q/K/V[b][g][h][i][dd]
    const int cwb = cBase + wn * 32;
    const int s2 = cwb >> 8, h = (cwb >> 5) & 7;
    float* dst = (s2 == 0) ? g_Q : ((s2 == 1) ? g_K : g_V);
#pragma unroll
    for (int mt = 0; mt < 2; mt++) {
#pragma unroll
        for (int r = 0; r < 2; r++) {
            int j = jBase + wm * 32 + mt * 16 + g + r * 8;
            int gg = j >> 10, i = j & 1023;
            size_t off = (((size_t)(b * GG + gg) * HH + h) * NG + i) * DD;
#pragma unroll
            for (int nt = 0; nt < 4; nt++) {
                *(float2*)&dst[off + nt * 8 + 2 * t] =
                    make_float2(acc[mt][nt][r * 2], acc[mt][nt][r * 2 + 1]);
            }
        }
    }
}

// ---------------------------------------------------------------------------
// Kernel 2: flash attention per (bgh, 64-row q-block). 4 warps, 16 q rows each.
// 3xTF32 via smem-level hi/lo split of K and transposed V; all fragments via
// ldmatrix. Ps aliases the Ks region. grid (16, 128), 128 threads.
// ---------------------------------------------------------------------------
#define KPITCH 36
#define VPITCH 68
#define PPITCH 68

__global__ __launch_bounds__(128) void attn_kernel()
{
    const int qblk = blockIdx.x;
    const int bgh  = blockIdx.y;
    const float* Qb = g_Q + (size_t)bgh * NG * DD + (size_t)qblk * 64 * DD;
    const float* Kb = g_K + (size_t)bgh * NG * DD;
    const float* Vb = g_V + (size_t)bgh * NG * DD;

    __shared__ float sm[8960];
    float* KsH = sm;                 // [64][36]
    float* KsL = sm + 2304;          // [64][36]
    float* VTH = sm + 4608;          // [32][68] (V transposed: [d][kv])
    float* VTL = sm + 6784;          // [32][68]
    float* Ps  = sm;                 // [64][68] aliases Ks (dead after S)

    const int tid = threadIdx.x;
    const int warp = tid >> 5, lane = tid & 31;
    const int g = lane >> 2, t = lane & 3;
    const int mat = lane >> 3, r8 = lane & 7;
    const int rbase = warp * 16;

    // Q fragments (pre-scaled, hi/lo split), resident in registers
    uint32_t qhi[4][4], qlo[4][4];
    {
        const float* Qw = Qb + rbase * DD;
#pragma unroll
        for (int ks = 0; ks < 4; ks++) {
            split_tf32(Qw[g * 32 + ks * 8 + t] * SCALE,           qhi[ks][0], qlo[ks][0]);
            split_tf32(Qw[(g + 8) * 32 + ks * 8 + t] * SCALE,     qhi[ks][1], qlo[ks][1]);
            split_tf32(Qw[g * 32 + ks * 8 + t + 4] * SCALE,       qhi[ks][2], qlo[ks][2]);
            split_tf32(Qw[(g + 8) * 32 + ks * 8 + t + 4] * SCALE, qhi[ks][3], qlo[ks][3]);
        }
    }

    // ldmatrix lane base addresses
    const uint32_t kAddrH = sptr(KsH + ((mat >> 1) * 8 + r8) * KPITCH + (mat & 1) * 4);
    const uint32_t kAddrL = kAddrH + 2304u * 4u;
    const uint32_t vAddrH = sptr(VTH + ((mat >> 1) * 8 + r8) * VPITCH + (mat & 1) * 4);
    const uint32_t vAddrL = vAddrH + 2176u * 4u;
    const uint32_t pAddr  = sptr(Ps + (rbase + (mat & 1) * 8 + r8) * PPITCH + (mat >> 1) * 4);

    // fill-phase indices
    const int kvK = tid >> 1,  khK = (tid & 1) * 16;
    const int kvV = tid & 63,  dqV = (tid >> 6) * 16;

    float m0 = -1e30f, m1 = -1e30f, l0 = 0.f, l1 = 0.f;
    float oc[4][4] = {};

    for (int kb = 0; kb < 16; kb++) {
        __syncthreads();  // prev-iter PV consumers done before refill
        // --- fill K (hi/lo split, [kv][d]) ---
        {
            const float* Kp = Kb + kb * 2048 + kvK * 32 + khK;
#pragma unroll
            for (int q4 = 0; q4 < 4; q4++) {
                float4 v = *(const float4*)(Kp + q4 * 4);
                uint32_t h, l;
                float4 h4, l4;
                split_tf32(v.x, h, l); h4.x = __uint_as_float(h); l4.x = __uint_as_float(l);
                split_tf32(v.y, h, l); h4.y = __uint_as_float(h); l4.y = __uint_as_float(l);
                split_tf32(v.z, h, l); h4.z = __uint_as_float(h); l4.z = __uint_as_float(l);
                split_tf32(v.w, h, l); h4.w = __uint_as_float(h); l4.w = __uint_as_float(l);
                *(float4*)&KsH[kvK * KPITCH + khK + q4 * 4] = h4;
                *(float4*)&KsL[kvK * KPITCH + khK + q4 * 4] = l4;
            }
        }
        // --- fill V transposed (hi/lo split, [d][kv]) ---
        {
            const float* Vp = Vb + kb * 2048 + kvV * 32 + dqV;
#pragma unroll
            for (int q4 = 0; q4 < 4; q4++) {
                float4 v = *(const float4*)(Vp + q4 * 4);
                int d0 = dqV + q4 * 4;
                uint32_t h, l;
                split_tf32(v.x, h, l);
                VTH[(d0 + 0) * VPITCH + kvV] = __uint_as_float(h);
                VTL[(d0 + 0) * VPITCH + kvV] = __uint_as_float(l);
                split_tf32(v.y, h, l);
                VTH[(d0 + 1) * VPITCH + kvV] = __uint_as_float(h);
                VTL[(d0 + 1) * VPITCH + kvV] = __uint_as_float(l);
                split_tf32(v.z, h, l);
                VTH[(d0 + 2) * VPITCH + kvV] = __uint_as_float(h);
                VTL[(d0 + 2) * VPITCH + kvV] = __uint_as_float(l);
                split_tf32(v.w, h, l);
                VTH[(d0 + 3) * VPITCH + kvV] = __uint_as_float(h);
                VTL[(d0 + 3) * VPITCH + kvV] = __uint_as_float(l);
            }
        }
        __syncthreads();

        // --- S = Q K^T (3xTF32, fragments via ldmatrix) ---
        float sc[8][4];
#pragma unroll
        for (int nt = 0; nt < 8; nt++)
            sc[nt][0] = sc[nt][1] = sc[nt][2] = sc[nt][3] = 0.f;
#pragma unroll
        for (int ks = 0; ks < 4; ks++) {
#pragma unroll
            for (int np = 0; np < 4; np++) {
                uint32_t kh[4], kl[4];
                ldsm4(kAddrH + (uint32_t)(np * 16 * KPITCH + ks * 8) * 4,
                      kh[0], kh[1], kh[2], kh[3]);
                ldsm4(kAddrL + (uint32_t)(np * 16 * KPITCH + ks * 8) * 4,
                      kl[0], kl[1], kl[2], kl[3]);
                mma8(sc[np * 2],     qhi[ks], kh[0], kh[1]);
                mma8(sc[np * 2],     qhi[ks], kl[0], kl[1]);
                mma8(sc[np * 2],     qlo[ks], kh[0], kh[1]);
                mma8(sc[np * 2 + 1], qhi[ks], kh[2], kh[3]);
                mma8(sc[np * 2 + 1], qhi[ks], kl[2], kl[3]);
                mma8(sc[np * 2 + 1], qlo[ks], kh[2], kh[3]);
            }
        }

        // --- online softmax (registers only) ---
        float rmax0 = -1e30f, rmax1 = -1e30f;
#pragma unroll
        for (int nt = 0; nt < 8; nt++) {
            rmax0 = fmaxf(rmax0, fmaxf(sc[nt][0], sc[nt][1]));
            rmax1 = fmaxf(rmax1, fmaxf(sc[nt][2], sc[nt][3]));
        }
        rmax0 = fmaxf(rmax0, __shfl_xor_sync(0xffffffffu, rmax0, 1));
        rmax0 = fmaxf(rmax0, __shfl_xor_sync(0xffffffffu, rmax0, 2));
        rmax1 = fmaxf(rmax1, __shfl_xor_sync(0xffffffffu, rmax1, 1));
        rmax1 = fmaxf(rmax1, __shfl_xor_sync(0xffffffffu, rmax1, 2));
        float mn0 = fmaxf(m0, rmax0), mn1 = fmaxf(m1, rmax1);
        float al0 = __expf(m0 - mn0), al1 = __expf(m1 - mn1);
        float s0 = 0.f, s1 = 0.f;
#pragma unroll
        for (int nt = 0; nt < 8; nt++) {
            sc[nt][0] = __expf(sc[nt][0] - mn0); s0 += sc[nt][0];
            sc[nt][1] = __expf(sc[nt][1] - mn0); s0 += sc[nt][1];
            sc[nt][2] = __expf(sc[nt][2] - mn1); s1 += sc[nt][2];
            sc[nt][3] = __expf(sc[nt][3] - mn1); s1 += sc[nt][3];
        }
        s0 += __shfl_xor_sync(0xffffffffu, s0, 1);
        s0 += __shfl_xor_sync(0xffffffffu, s0, 2);
        s1 += __shfl_xor_sync(0xffffffffu, s1, 1);
        s1 += __shfl_xor_sync(0xffffffffu, s1, 2);
        m0 = mn0; m1 = mn1;
        l0 = l0 * al0 + s0;
        l1 = l1 * al1 + s1;
#pragma unroll
        for (int nt = 0; nt < 4; nt++) {
            oc[nt][0] *= al0; oc[nt][1] *= al0;
            oc[nt][2] *= al1; oc[nt][3] *= al1;
        }

        __syncthreads();  // all warps done reading Ks before Ps (alias) is written

        // --- P -> smem (fp32, warp-private rows) ---
#pragma unroll
        for (int nt = 0; nt < 8; nt++) {
            *(float2*)&Ps[(rbase + g) * PPITCH + nt * 8 + 2 * t] =
                make_float2(sc[nt][0], sc[nt][1]);
            *(float2*)&Ps[(rbase + g + 8) * PPITCH + nt * 8 + 2 * t] =
                make_float2(sc[nt][2], sc[nt][3]);
        }
        __syncwarp();

        // --- O += P @ V (3xTF32) ---
#pragma unroll
        for (int ks = 0; ks < 8; ks++) {
            uint32_t p[4], ph[4], pl[4];
            ldsm4(pAddr + (uint32_t)(ks * 8) * 4, p[0], p[1], p[2], p[3]);
#pragma unroll
            for (int i = 0; i < 4; i++) split_tf32(__uint_as_float(p[i]), ph[i], pl[i]);
#pragma unroll
            for (int np = 0; np < 2; np++) {
                uint32_t vh[4], vl[4];
                ldsm4(vAddrH + (uint32_t)(np * 16 * VPITCH + ks * 8) * 4,
                      vh[0], vh[1], vh[2], vh[3]);
                ldsm4(vAddrL + (uint32_t)(np * 16 * VPITCH + ks * 8) * 4,
                      vl[0], vl[1], vl[2], vl[3]);
                mma8(oc[np * 2],     ph, vh[0], vh[1]);
                mma8(oc[np * 2],     ph, vl[0], vl[1]);
                mma8(oc[np * 2],     pl, vh[0], vh[1]);
                mma8(oc[np * 2 + 1], ph, vh[2], vh[3]);
                mma8(oc[np * 2 + 1], ph, vl[2], vl[3]);
                mma8(oc[np * 2 + 1], pl, vh[2], vh[3]);
            }
        }
    }

    // Finalize: o_perm[b, g*1024+i, h*32+dd]
    const int b = bgh >> 5, gg = (bgh >> 3) & 3, h = bgh & 7;
    float inv0 = 1.f / l0, inv1 = 1.f / l1;
    int i0 = qblk * 64 + rbase + g;
    size_t row0 = ((size_t)b * NN + (size_t)gg * NG + i0) * CC + h * DD;
    size_t row1 = row0 + (size_t)8 * CC;
#pragma unroll
    for (int nt = 0; nt < 4; nt++) {
        *(float2*)&g_O[row0 + nt * 8 + 2 * t] =
            make_float2(oc[nt][0] * inv0, oc[nt][1] * inv0);
        *(float2*)&g_O[row1 + nt * 8 + 2 * t] =
            make_float2(oc[nt][2] * inv1, oc[nt][3] * inv1);
    }
}

// ---------------------------------------------------------------------------
// Kernel 3: out[b, idx[j], :] = o_perm[b, j, :] @ w_proj^T + bias
// same tiling as qkv, inverse permutation fused as row scatter. grid (4, 128)
// ---------------------------------------------------------------------------
__global__ __launch_bounds__(256) void proj_kernel(
    const int* __restrict__ idx, const float* __restrict__ w,
    const float* __restrict__ bias, float* __restrict__ out)
{
    const int cBase = blockIdx.x * 64;
    const int rblk  = blockIdx.y;
    const int b     = rblk >> 5;
    const int jBase = (rblk & 31) * 128;

    __shared__ float As[128][36];
    __shared__ float Bs[64][36];
    __shared__ int   sidx[128];

    const int tid = threadIdx.x;
    const int warp = tid >> 5, lane = tid & 31;
    const int g = lane >> 2, t = lane & 3;
    const int wm = warp >> 1, wn = warp & 1;
    const int mat = lane >> 3, r8 = lane & 7;

    if (tid < 128) sidx[tid] = idx[jBase + tid];

    const float* arow = g_O + ((size_t)b * NN + jBase + (tid >> 1)) * CC + (tid & 1) * 16;
    const float* brow = w + (size_t)(cBase + (tid & 63)) * CC + (tid >> 6) * 8;
    const int ar = tid >> 1, akh = (tid & 1) * 16;
    const int br = tid & 63, bkh = (tid >> 6) * 8;

    float4 pa[4], pb[2];
#pragma unroll
    for (int i = 0; i < 4; i++) pa[i] = *(const float4*)(arow + i * 4);
    pb[0] = *(const float4*)(brow);
    pb[1] = *(const float4*)(brow + 4);

    const uint32_t aAddr = sptr(&As[wm * 32 + (mat & 1) * 8 + r8][(mat >> 1) * 4]);
    const uint32_t bAddr = sptr(&Bs[wn * 32 + (mat >> 1) * 8 + r8][(mat & 1) * 4]);

    float acc[2][4][4] = {};

    for (int s = 0; s < 8; s++) {
        __syncthreads();
        *(float4*)&As[ar][akh]      = pa[0];
        *(float4*)&As[ar][akh + 4]  = pa[1];
        *(float4*)&As[ar][akh + 8]  = pa[2];
        *(float4*)&As[ar][akh + 12] = pa[3];
        *(float4*)&Bs[br][bkh]      = pb[0];
        *(float4*)&Bs[br][bkh + 4]  = pb[1];
        __syncthreads();
        if (s < 7) {
            const float* an = arow + (s + 1) * 32;
#pragma unroll
            for (int i = 0; i < 4; i++) pa[i] = *(const float4*)(an + i * 4);
            pb[0] = *(const float4*)(brow + (s + 1) * 32);
            pb[1] = *(const float4*)(brow + (s + 1) * 32 + 4);
        }
#pragma unroll
        for (int ks = 0; ks < 4; ks++) {
            uint32_t af[2][4];
#pragma unroll
            for (int mt = 0; mt < 2; mt++) {
                ldsm4(aAddr + (uint32_t)(mt * 16 * 36 + ks * 8) * 4,
                      af[mt][0], af[mt][1], af[mt][2], af[mt][3]);
#pragma unroll
                for (int i = 0; i < 4; i++) af[mt][i] = to_tf32(__uint_as_float(af[mt][i]));
            }
#pragma unroll
            for (int np = 0; np < 2; np++) {
                uint32_t bf[4];
                ldsm4(bAddr + (uint32_t)(np * 16 * 36 + ks * 8) * 4,
                      bf[0], bf[1], bf[2], bf[3]);
#pragma unroll
                for (int i = 0; i < 4; i++) bf[i] = to_tf32(__uint_as_float(bf[i]));
                mma8(acc[0][np * 2],     af[0], bf[0], bf[1]);
                mma8(acc[1][np * 2],     af[1], bf[0], bf[1]);
                mma8(acc[0][np * 2 + 1], af[0], bf[2], bf[3]);
                mma8(acc[1][np * 2 + 1], af[1], bf[2], bf[3]);
            }
        }
    }

    // Epilogue: bias + inverse-permutation row scatter
    float2 bb[4];
#pragma unroll
    for (int nt = 0; nt < 4; nt++)
        bb[nt] = *(const float2*)&bias[cBase + wn * 32 + nt * 8 + 2 * t];

#pragma unroll
    for (int mt = 0; mt < 2; mt++) {
#pragma unroll
        for (int r = 0; r < 2; r++) {
            int jl = wm * 32 + mt * 16 + g + r * 8;
            int orow = sidx[jl];
            size_t base = ((size_t)b * NN + orow) * CC + cBase + wn * 32;
#pragma unroll
            for (int nt = 0; nt < 4; nt++) {
                *(float2*)&out[base + nt * 8 + 2 * t] =
                    make_float2(acc[mt][nt][r * 2] + bb[nt].x,
                                acc[mt][nt][r * 2 + 1] + bb[nt].y);
            }
        }
    }
}

// ---------------------------------------------------------------------------
extern "C" void kernel_launch(void* const* d_in, const int* in_sizes, int n_in,
                              void* d_out, int out_size)
{
    (void)in_sizes; (void)n_in; (void)out_size;
    const float* x      = (const float*)d_in[0];
    const int*   idx    = (const int*)d_in[1];
    const float* w_qkv  = (const float*)d_in[2];
    const float* w_proj = (const float*)d_in[3];
    const float* b_proj = (const float*)d_in[4];
    float* out = (float*)d_out;

    qkv_kernel<<<dim3(12, 128), 256>>>(x, idx, w_qkv);
    attn_kernel<<<dim3(16, 128), 128>>>();
    proj_kernel<<<dim3(4, 128), 256>>>(idx, w_proj, b_proj, out);
}